// round 3
// baseline (speedup 1.0000x reference)
#include <cuda_runtime.h>
#include <cuda_bf16.h>

#define NN 100000
#define EE 3200000
#define F_IN 512
#define H1 4
#define C1 8
#define D1 32   // H1*C1
#define D2 8    // num classes
#define ETOT (EE + NN)

typedef unsigned long long ull;

// -------- scratch (device globals; no allocation allowed) --------
__device__ int   g_deg[NN];
__device__ int   g_off[NN];
__device__ int   g_bsum[128];
__device__ int   g_cur[NN];
__device__ int   g_srcs[ETOT];
__device__ float g_xp1[NN * D1];
__device__ float g_as1[NN * H1];
__device__ float g_ad1[NN * H1];
__device__ float g_xp2[NN * D2];
__device__ float g_as2[NN];
__device__ float g_ad2[NN];

// -------- streams/events for capture fork-join (created pre-main; no device mem) ----
static cudaStream_t g_s1;
static cudaEvent_t g_ev0, g_ev1;
namespace {
struct InitStreams {
    InitStreams() {
        cudaStreamCreateWithFlags(&g_s1, cudaStreamNonBlocking);
        cudaEventCreateWithFlags(&g_ev0, cudaEventDisableTiming);
        cudaEventCreateWithFlags(&g_ev1, cudaEventDisableTiming);
    }
} s_initStreams;
}

__device__ __forceinline__ float lrelu(float v) { return v > 0.f ? v : 0.2f * v; }

__device__ __forceinline__ ull fma2(ull a, ull b, ull c) {
    ull d;
    asm("fma.rn.f32x2 %0, %1, %2, %3;" : "=l"(d) : "l"(a), "l"(b), "l"(c));
    return d;
}
__device__ __forceinline__ ull pack2(float v) {
    ull r; unsigned u = __float_as_uint(v);
    asm("mov.b64 %0, {%1,%1};" : "=l"(r) : "r"(u));
    return r;
}
__device__ __forceinline__ void unpack2(ull v, float& lo, float& hi) {
    unsigned a, b;
    asm("mov.b64 {%0,%1}, %2;" : "=r"(a), "=r"(b) : "l"(v));
    lo = __uint_as_float(a); hi = __uint_as_float(b);
}

// ================= CSR build =================
__global__ void init_deg_kernel() {
    int i = blockIdx.x * blockDim.x + threadIdx.x;
    if (i < NN) g_deg[i] = 1;   // self-loop
}

__global__ void hist_kernel(const int* __restrict__ ei) {
    int e = blockIdx.x * blockDim.x + threadIdx.x;
    if (e < EE) atomicAdd(&g_deg[ei[EE + e]], 1);
}

// 98 blocks x 256 threads x 4 items = 100352 slots
__global__ __launch_bounds__(256) void scan_local_kernel() {
    __shared__ int ssum[256];
    int b = blockIdx.x, t = threadIdx.x;
    int base = b * 1024 + t * 4;
    int v[4];
#pragma unroll
    for (int j = 0; j < 4; j++) v[j] = (base + j < NN) ? g_deg[base + j] : 0;
    int run = 0;
#pragma unroll
    for (int j = 0; j < 4; j++) { int tmp = v[j]; v[j] = run; run += tmp; }
    ssum[t] = run;
    __syncthreads();
#pragma unroll
    for (int s = 1; s < 256; s <<= 1) {
        int x = (t >= s) ? ssum[t - s] : 0;
        __syncthreads();
        ssum[t] += x;
        __syncthreads();
    }
    int toff = (t > 0) ? ssum[t - 1] : 0;
#pragma unroll
    for (int j = 0; j < 4; j++)
        if (base + j < NN) g_off[base + j] = toff + v[j];
    if (t == 255) g_bsum[b] = ssum[255];
}

__global__ void scan_bsum_kernel() {
    __shared__ int s[128];
    int t = threadIdx.x;
    s[t] = (t < 98) ? g_bsum[t] : 0;
    __syncthreads();
#pragma unroll
    for (int st = 1; st < 128; st <<= 1) {
        int x = (t >= st) ? s[t - st] : 0;
        __syncthreads();
        s[t] += x;
        __syncthreads();
    }
    if (t < 98) g_bsum[t] = (t > 0) ? s[t - 1] : 0;
}

__global__ void scan_add_kernel() {
    int i = blockIdx.x * blockDim.x + threadIdx.x;
    if (i >= NN) return;
    int off = g_off[i] + g_bsum[i >> 10];
    g_off[i] = off;
    g_srcs[off] = i;       // self-loop placed first
    g_cur[i] = off + 1;
}

__global__ void scatter_kernel(const int* __restrict__ ei) {
    int e = blockIdx.x * blockDim.x + threadIdx.x;
    if (e >= EE) return;
    int dst = ei[EE + e];
    int src = ei[e];
    int pos = atomicAdd(&g_cur[dst], 1);
    g_srcs[pos] = src;
}

// ================= GEMM1 (f32x2) + fused att1 =================
__global__ __launch_bounds__(256) void gemm1_kernel(const float* __restrict__ x,
                                                    const float* __restrict__ W,
                                                    const float* __restrict__ att_src,
                                                    const float* __restrict__ att_dst) {
    __shared__ float xs[256][17];
    __shared__ float ws[16][32];
    __shared__ float s_as[32], s_ad[32];
    int t = threadIdx.x;
    int tx = t & 3;        // head / col group (8 cols)
    int ty = t >> 2;       // row group (4 rows)
    int row0 = blockIdx.x * 256;
    if (t < 32) { s_as[t] = att_src[t]; s_ad[t] = att_dst[t]; }

    ull acc2[4][4];
#pragma unroll
    for (int i = 0; i < 4; i++)
#pragma unroll
        for (int j = 0; j < 4; j++) acc2[i][j] = 0ull;

    for (int k0 = 0; k0 < F_IN; k0 += 16) {
#pragma unroll
        for (int i = 0; i < 4; i++) {
            int idx = t + 256 * i;
            int r = idx >> 2;
            int c4 = idx & 3;
            float4 v = make_float4(0.f, 0.f, 0.f, 0.f);
            int gr = row0 + r;
            if (gr < NN) v = *(const float4*)(x + (size_t)gr * F_IN + k0 + c4 * 4);
            xs[r][c4 * 4 + 0] = v.x;
            xs[r][c4 * 4 + 1] = v.y;
            xs[r][c4 * 4 + 2] = v.z;
            xs[r][c4 * 4 + 3] = v.w;
        }
#pragma unroll
        for (int i = 0; i < 2; i++) {
            int idx = t + 256 * i;
            int r = idx >> 5, c = idx & 31;
            ws[r][c] = W[(k0 + r) * 32 + c];
        }
        __syncthreads();
#pragma unroll
        for (int kk = 0; kk < 16; kk++) {
            const ull* wp = (const ull*)(&ws[kk][tx * 8]);
            ull w0 = wp[0], w1 = wp[1], w2 = wp[2], w3 = wp[3];
#pragma unroll
            for (int i = 0; i < 4; i++) {
                ull xv2 = pack2(xs[ty * 4 + i][kk]);
                acc2[i][0] = fma2(xv2, w0, acc2[i][0]);
                acc2[i][1] = fma2(xv2, w1, acc2[i][1]);
                acc2[i][2] = fma2(xv2, w2, acc2[i][2]);
                acc2[i][3] = fma2(xv2, w3, acc2[i][3]);
            }
        }
        __syncthreads();
    }
#pragma unroll
    for (int i = 0; i < 4; i++) {
        int gr = row0 + ty * 4 + i;
        if (gr >= NN) continue;
        float a[8];
#pragma unroll
        for (int j = 0; j < 4; j++) unpack2(acc2[i][j], a[2 * j], a[2 * j + 1]);
        float as = 0.f, ad = 0.f;
#pragma unroll
        for (int j = 0; j < 8; j++) {
            as += a[j] * s_as[tx * 8 + j];
            ad += a[j] * s_ad[tx * 8 + j];
        }
        float* op = g_xp1 + (size_t)gr * D1 + tx * 8;
        *(float4*)(op)     = make_float4(a[0], a[1], a[2], a[3]);
        *(float4*)(op + 4) = make_float4(a[4], a[5], a[6], a[7]);
        g_as1[gr * 4 + tx] = as;
        g_ad1[gr * 4 + tx] = ad;
    }
}

// ===== layer-1 aggregation (warp/dst) fused with bias+ELU+GEMM2+att2 epilogue =====
// block = 256 threads = 8 warps = 8 destination nodes; grid = NN/8 = 12500 exact
__global__ __launch_bounds__(256) void agg1_kernel(const float* __restrict__ b1,
                                                   const float* __restrict__ W2,
                                                   const float* __restrict__ as2w,
                                                   const float* __restrict__ ad2w) {
    __shared__ float h_s[8][33];       // padded: conflict-free strided reads
    __shared__ float w2s[D1 * D2];
    __shared__ float b1s[D1];
    __shared__ float a2s[D2], a2d[D2];
    int t = threadIdx.x;
    if (t < D1 * D2) w2s[t] = W2[t];
    if (t < D1) b1s[t] = b1[t];
    if (t < D2) { a2s[t] = as2w[t]; a2d[t] = ad2w[t]; }

    int wl = t >> 5;
    int w = blockIdx.x * 8 + wl;       // destination node
    int lane = t & 31;
    int g = lane >> 2;                 // edge slot 0..7
    int h = lane & 3;                  // head
    int beg = g_off[w];
    int end = (w + 1 < NN) ? g_off[w + 1] : ETOT;
    float ad = g_ad1[w * 4 + h];
    float a0 = 0.f, a1 = 0.f, a2 = 0.f, a3 = 0.f;
    float a4 = 0.f, a5 = 0.f, a6 = 0.f, a7 = 0.f;
    float den = 0.f;
    for (int i = beg + g; i < end; i += 8) {
        int src = g_srcs[i];
        float as = g_as1[src * 4 + h];
        float s = __expf(lrelu(as + ad));
        den += s;
        const float4* p = (const float4*)(g_xp1 + (size_t)src * D1 + h * C1);
        float4 u = p[0], v = p[1];
        a0 += s * u.x; a1 += s * u.y; a2 += s * u.z; a3 += s * u.w;
        a4 += s * v.x; a5 += s * v.y; a6 += s * v.z; a7 += s * v.w;
    }
#pragma unroll
    for (int m = 4; m < 32; m <<= 1) {
        den += __shfl_xor_sync(0xffffffffu, den, m);
        a0 += __shfl_xor_sync(0xffffffffu, a0, m);
        a1 += __shfl_xor_sync(0xffffffffu, a1, m);
        a2 += __shfl_xor_sync(0xffffffffu, a2, m);
        a3 += __shfl_xor_sync(0xffffffffu, a3, m);
        a4 += __shfl_xor_sync(0xffffffffu, a4, m);
        a5 += __shfl_xor_sync(0xffffffffu, a5, m);
        a6 += __shfl_xor_sync(0xffffffffu, a6, m);
        a7 += __shfl_xor_sync(0xffffffffu, a7, m);
    }
    if (g == 0) {
        float inv = 1.f / den;
        float* o = &h_s[wl][h * C1];
        o[0] = a0 * inv; o[1] = a1 * inv; o[2] = a2 * inv; o[3] = a3 * inv;
        o[4] = a4 * inv; o[5] = a5 * inv; o[6] = a6 * inv; o[7] = a7 * inv;
    }
    __syncthreads();

    // epilogue: 8 threads, one node each — bias + ELU + GEMM2 (32x8) + att2 dots
    if (t < 8) {
        int node = blockIdx.x * 8 + t;
        float hv[D1];
#pragma unroll
        for (int k = 0; k < D1; k++) {
            float v = h_s[t][k] + b1s[k];
            hv[k] = v > 0.f ? v : expm1f(v);   // elu
        }
        float xp[D2];
#pragma unroll
        for (int c = 0; c < D2; c++) xp[c] = 0.f;
#pragma unroll
        for (int k = 0; k < D1; k++)
#pragma unroll
            for (int c = 0; c < D2; c++) xp[c] += hv[k] * w2s[k * D2 + c];
        float as = 0.f, ads = 0.f;
#pragma unroll
        for (int c = 0; c < D2; c++) { as += xp[c] * a2s[c]; ads += xp[c] * a2d[c]; }
        *(float4*)(g_xp2 + (size_t)node * D2)     = make_float4(xp[0], xp[1], xp[2], xp[3]);
        *(float4*)(g_xp2 + (size_t)node * D2 + 4) = make_float4(xp[4], xp[5], xp[6], xp[7]);
        g_as2[node] = as;
        g_ad2[node] = ads;
    }
}

// ================= layer-2 aggregation: warp per dst =================
__global__ __launch_bounds__(256) void agg2_kernel(float* __restrict__ out,
                                                   const float* __restrict__ b2) {
    int w = (blockIdx.x * blockDim.x + threadIdx.x) >> 5;
    if (w >= NN) return;
    int lane = threadIdx.x & 31;
    int beg = g_off[w];
    int end = (w + 1 < NN) ? g_off[w + 1] : ETOT;
    float ad = g_ad2[w];
    float a0 = 0.f, a1 = 0.f, a2 = 0.f, a3 = 0.f;
    float a4 = 0.f, a5 = 0.f, a6 = 0.f, a7 = 0.f;
    float den = 0.f;
    for (int i = beg + lane; i < end; i += 32) {
        int src = g_srcs[i];
        float s = __expf(lrelu(g_as2[src] + ad));
        den += s;
        const float4* p = (const float4*)(g_xp2 + (size_t)src * D2);
        float4 u = p[0], v = p[1];
        a0 += s * u.x; a1 += s * u.y; a2 += s * u.z; a3 += s * u.w;
        a4 += s * v.x; a5 += s * v.y; a6 += s * v.z; a7 += s * v.w;
    }
#pragma unroll
    for (int m = 1; m < 32; m <<= 1) {
        den += __shfl_xor_sync(0xffffffffu, den, m);
        a0 += __shfl_xor_sync(0xffffffffu, a0, m);
        a1 += __shfl_xor_sync(0xffffffffu, a1, m);
        a2 += __shfl_xor_sync(0xffffffffu, a2, m);
        a3 += __shfl_xor_sync(0xffffffffu, a3, m);
        a4 += __shfl_xor_sync(0xffffffffu, a4, m);
        a5 += __shfl_xor_sync(0xffffffffu, a5, m);
        a6 += __shfl_xor_sync(0xffffffffu, a6, m);
        a7 += __shfl_xor_sync(0xffffffffu, a7, m);
    }
    if (lane == 0) {
        float inv = 1.f / den;
        float* o = out + (size_t)w * D2;
        *(float4*)(o)     = make_float4(a0 * inv + b2[0], a1 * inv + b2[1],
                                        a2 * inv + b2[2], a3 * inv + b2[3]);
        *(float4*)(o + 4) = make_float4(a4 * inv + b2[4], a5 * inv + b2[5],
                                        a6 * inv + b2[6], a7 * inv + b2[7]);
    }
}

extern "C" void kernel_launch(void* const* d_in, const int* in_sizes, int n_in,
                              void* d_out, int out_size) {
    const float* x        = (const float*)d_in[0];
    const int*   ei       = (const int*)d_in[1];
    const float* W1       = (const float*)d_in[2];
    const float* att_src1 = (const float*)d_in[3];
    const float* att_dst1 = (const float*)d_in[4];
    const float* b1       = (const float*)d_in[5];
    const float* W2       = (const float*)d_in[6];
    const float* att_src2 = (const float*)d_in[7];
    const float* att_dst2 = (const float*)d_in[8];
    const float* b2       = (const float*)d_in[9];
    float* out = (float*)d_out;

    const int TB = 256;
    int gN = (NN + TB - 1) / TB;           // 391
    int gE = (EE + TB - 1) / TB;           // 12500
    int gW = (NN * 32 + TB - 1) / TB;      // 12500 (warp per node)

    // fork: GEMM1 on side stream, CSR build on main stream
    cudaEventRecord(g_ev0, 0);
    cudaStreamWaitEvent(g_s1, g_ev0, 0);
    gemm1_kernel<<<gN, 256, 0, g_s1>>>(x, W1, att_src1, att_dst1);
    cudaEventRecord(g_ev1, g_s1);

    init_deg_kernel<<<gN, TB>>>();
    hist_kernel<<<gE, TB>>>(ei);
    scan_local_kernel<<<98, 256>>>();
    scan_bsum_kernel<<<1, 128>>>();
    scan_add_kernel<<<gN, TB>>>();
    scatter_kernel<<<gE, TB>>>(ei);

    // join: aggregation needs both legs
    cudaStreamWaitEvent(0, g_ev1, 0);
    agg1_kernel<<<12500, 256>>>(b1, W2, att_src2, att_dst2);
    agg2_kernel<<<gW, TB>>>(out, b2);
}